// round 12
// baseline (speedup 1.0000x reference)
#include <cuda_runtime.h>
#include <cuda_bf16.h>
#include <math.h>

#define NSAMP 64
#define TLEN  512
#define DDIM  16
#define NDIAG 1023
#define BIGL  1.0e10f
#define LOG2E 1.4426950408889634f
#define LN2   0.6931471805599453f
#define NPHASE 135   // 8 global warps: gw=7 reaches diag 1022 at phase 134

__device__ float g_res[NSAMP];

typedef unsigned long long ull;

__device__ __forceinline__ float ex2f(float x){ float y; asm("ex2.approx.ftz.f32 %0, %1;" : "=f"(y) : "f"(x)); return y; }
__device__ __forceinline__ float lg2f(float x){ float y; asm("lg2.approx.ftz.f32 %0, %1;" : "=f"(y) : "f"(x)); return y; }
__device__ __forceinline__ ull mul2(ull a, ull b){ ull d; asm("mul.rn.f32x2 %0, %1, %2;" : "=l"(d) : "l"(a), "l"(b)); return d; }
__device__ __forceinline__ ull add2(ull a, ull b){ ull d; asm("add.rn.f32x2 %0, %1, %2;" : "=l"(d) : "l"(a), "l"(b)); return d; }
__device__ __forceinline__ ull fma2(ull a, ull b, ull c){ ull d; asm("fma.rn.f32x2 %0, %1, %2, %3;" : "=l"(d) : "l"(a), "l"(b), "l"(c)); return d; }
#define UNPK(LO, HI, P) asm("mov.b64 {%0, %1}, %2;" : "=f"(LO), "=f"(HI) : "l"(P))

// Z permutation: row z -> slot (z>>1) + 256*(z&1); lanes (2 rows apart) hit
// consecutive slots; 18-float pitch => stride-18 banks, conflict-free.
#define ZSLOT(z) (((z) >> 1) + 256 * ((z) & 1))

// ---------------------------------------------------------------------------
// FUSED soft-DTW, 2-CTA cluster per sample. CTA rank r owns rows [256r,256r+256).
// 128 threads = 4 warps/CTA (1/SMSP), 2 cells/thread. Global staircase over
// 8 warps (lag 8). Cross-CTA boundary: CTA0-warp3 remote-writes CTA1's
// rings[0] + release phase counter; CTA1-warp0 acquires once per phase.
// Reverse counter gives back-pressure (128-slot rings; CTA0 <= CTA1+8).
// ---------------------------------------------------------------------------
__global__ void __launch_bounds__(128) __cluster_dims__(2, 1, 1)
fused_dp_kernel(const float* __restrict__ X, const float* __restrict__ Z)
{
    __shared__ float zsm[512 * 18];
    __shared__ float rings[5][128];
    __shared__ int   cnt_fwd;    // CTA1: written remotely by CTA0
    __shared__ int   cnt_back;   // CTA0: written remotely by CTA1

    const int tid  = threadIdx.x;
    const int w    = tid >> 5;
    const int lane = tid & 31;
    unsigned rank;
    asm("mov.u32 %0, %%cluster_ctarank;" : "=r"(rank));
    const int n    = blockIdx.x >> 1;
    const int gw   = (int)rank * 4 + w;            // global staircase warp id
    const int row0 = (int)rank * 256 + 2 * tid;    // first of this thread's 2 rows
    const bool edge = (rank == 0 && w == 3);       // publishes row 255 to CTA1

    // ---- stage Z (full) into permuted smem (+ z2*log2e at offset 16) ----
    for (int r = tid; r < 512; r += 128) {
        const float* zg = Z + r * 16;
        float vals[16]; float s2 = 0.f;
        #pragma unroll
        for (int k = 0; k < 16; k++) { float v = zg[k]; vals[k] = v; s2 = fmaf(v, v, s2); }
        float* dst = zsm + ZSLOT(r) * 18;
        #pragma unroll
        for (int k = 0; k < 16; k++) dst[k] = vals[k];
        dst[16] = s2 * LOG2E;
    }
    for (int i = tid; i < 5 * 128; i += 128) (&rings[0][0])[i] = BIGL;
    if (tid == 0) { cnt_fwd = -1; cnt_back = -1; }

    // ---- stage this thread's 2 X rows into packed registers ----
    ull xp[2][8]; float x2L[2];
    {
        const ull* Xp = (const ull*)(X + ((size_t)n * TLEN + row0) * DDIM);
        #pragma unroll
        for (int c = 0; c < 2; c++) {
            float s2 = 0.f;
            #pragma unroll
            for (int k = 0; k < 8; k++) {
                ull p = Xp[c * 8 + k]; xp[c][k] = p;
                float lo, hi; UNPK(lo, hi, p);
                s2 = fmaf(lo, lo, fmaf(hi, hi, s2));
            }
            x2L[c] = s2 * LOG2E;
        }
    }

    float rc0 = BIGL, rc1 = BIGL, rd0 = BIGL, rd1 = BIGL;
    if (rank == 0 && tid == 0) rd0 = 0.0f;         // corner R[0][0]
    float resv = BIGL;

    float* ringr = &rings[w][0];
    float* ringw = &rings[w + 1][0];

    __syncthreads();
    asm volatile("barrier.cluster.arrive.aligned;" ::: "memory");
    asm volatile("barrier.cluster.wait.aligned;" ::: "memory");

    // remote addresses in the peer CTA
    const unsigned lring0 = (unsigned)__cvta_generic_to_shared(&rings[0][0]);
    const unsigned lcntf  = (unsigned)__cvta_generic_to_shared(&cnt_fwd);
    const unsigned lcntb  = (unsigned)__cvta_generic_to_shared(&cnt_back);
    const unsigned peer = rank ^ 1u;
    unsigned r_ring0, r_cntf, r_cntb;
    asm("mapa.shared::cluster.u32 %0, %1, %2;" : "=r"(r_ring0) : "r"(lring0), "r"(peer));
    asm("mapa.shared::cluster.u32 %0, %1, %2;" : "=r"(r_cntf)  : "r"(lcntf),  "r"(peer));
    asm("mapa.shared::cluster.u32 %0, %1, %2;" : "=r"(r_cntb)  : "r"(lcntb),  "r"(peer));

    ull   zr[2][8];     // 2-row Z cache; slot parity = (z - kstart + row0) & 1
    float dD[2][2];     // D ping-pong: dD[J&1][cell]

#define ZLOAD(SLOT, JUC)                                                       \
    {                                                                          \
        int jc = (JUC); jc = jc < 0 ? 0 : (jc > 511 ? 511 : jc);               \
        const ull* zp = (const ull*)(zsm + ZSLOT(jc) * 18);                    \
        zr[SLOT][0] = zp[0]; zr[SLOT][1] = zp[1];                              \
        zr[SLOT][2] = zp[2]; zr[SLOT][3] = zp[3];                              \
        zr[SLOT][4] = zp[4]; zr[SLOT][5] = zp[5];                              \
        zr[SLOT][6] = zp[6]; zr[SLOT][7] = zp[7];                              \
    }

#define DCOMP(DST, C, SLOT, JUC)                                               \
    {                                                                          \
        int jc = (JUC); jc = jc < 0 ? 0 : (jc > 511 ? 511 : jc);               \
        float z2v = zsm[ZSLOT(jc) * 18 + 16];                                  \
        ull a0 = mul2(xp[C][0], zr[SLOT][0]);                                  \
        ull a1 = mul2(xp[C][1], zr[SLOT][1]);                                  \
        a0 = fma2(xp[C][2], zr[SLOT][2], a0);                                  \
        a1 = fma2(xp[C][3], zr[SLOT][3], a1);                                  \
        a0 = fma2(xp[C][4], zr[SLOT][4], a0);                                  \
        a1 = fma2(xp[C][5], zr[SLOT][5], a1);                                  \
        a0 = fma2(xp[C][6], zr[SLOT][6], a0);                                  \
        a1 = fma2(xp[C][7], zr[SLOT][7], a1);                                  \
        a0 = add2(a0, a1);                                                     \
        float lo, hi; UNPK(lo, hi, a0);                                        \
        float dot = lo + hi;                                                   \
        (DST) = fmaxf(fmaf(dot, -2.0f * LOG2E, x2L[C] + z2v), 0.0f);           \
    }

    // ---- prologue: prime Z cache + dD[0] for this warp's first diag ----
    const int kstart = -8 * gw;
    ZLOAD(1, kstart - row0 - 1)
    ZLOAD(0, kstart - row0)
    DCOMP(dD[0][0], 0, 0, kstart - row0)
    DCOMP(dD[0][1], 1, 1, kstart - row0 - 1)
    ZLOAD(1, kstart - row0 + 1)

#define DP_STEP(J)                                                             \
    {                                                                          \
        const int cur = kwb + (J);                                             \
        const float bval = ringr[(cur - 1) & 127];                             \
        float upsh = __shfl_up_sync(0xffffffffu, rc1, 1);                      \
        const float u0 = (lane == 0) ? bval : upsh;                            \
        const float u1 = rc0;                                                  \
        {                                                                      \
            float m  = fminf(fminf(u0, rc0), rd0);                             \
            float Mx = fmaxf(fmaxf(u0, rc0), rd0);                             \
            float mid = ((u0 + rc0) + rd0) - m - Mx;                           \
            float s  = 1.0f + ex2f(m - mid) + ex2f(m - Mx);                    \
            float v  = (dD[(J) & 1][0] + m) - lg2f(s);                         \
            if ((unsigned)(cur - row0) >= 512u) v = BIGL;                      \
            rd0 = u0; rc0 = v;                                                 \
        }                                                                      \
        {                                                                      \
            float m  = fminf(fminf(u1, rc1), rd1);                             \
            float Mx = fmaxf(fmaxf(u1, rc1), rd1);                             \
            float mid = ((u1 + rc1) + rd1) - m - Mx;                           \
            float s  = 1.0f + ex2f(m - mid) + ex2f(m - Mx);                    \
            float v  = (dD[(J) & 1][1] + m) - lg2f(s);                         \
            if ((unsigned)(cur - row0 - 1) >= 512u) v = BIGL;                  \
            rd1 = u1; rc1 = v;                                                 \
        }                                                                      \
        if (cur == NDIAG - 1) resv = rc1;                                      \
        if (lane == 31 && (unsigned)cur < 1023u) {                             \
            if (edge)                                                          \
                asm volatile("st.shared::cluster.b32 [%0], %1;"                \
                    :: "r"(r_ring0 + ((unsigned)cur & 127u) * 4u),             \
                       "r"(__float_as_uint(rc1)) : "memory");                  \
            else ringw[cur & 127] = rc1;                                       \
        }                                                                      \
        DCOMP(dD[((J) + 1) & 1][0], 0, ((J) + 1) & 1, cur + 1 - row0)          \
        DCOMP(dD[((J) + 1) & 1][1], 1, ((J) + 0) & 1, cur - row0)              \
        ZLOAD((J) & 1, cur + 2 - row0)                                         \
    }

    #pragma unroll 1
    for (int p = 0; p < NPHASE; ++p) {
        // forward wait: CTA1-warp0 needs CTA0 phase p-1 published (rare-path)
        if (rank == 1 && w == 0 && lane == 0) {
            int c;
            do { asm volatile("ld.acquire.cluster.shared::cta.b32 %0, [%1];"
                              : "=r"(c) : "r"(lcntf) : "memory"); } while (c < p - 1);
        }
        // back-pressure: CTA0 must stay within 8 phases of CTA1 (128-slot ring)
        if (rank == 0 && w == 3 && lane == 31) {
            int c;
            do { asm volatile("ld.acquire.cluster.shared::cta.b32 %0, [%1];"
                              : "=r"(c) : "r"(lcntb) : "memory"); } while (c < p - 8);
        }
        const int kwb = 8 * p - 8 * gw;
        DP_STEP(0) DP_STEP(1) DP_STEP(2) DP_STEP(3)
        DP_STEP(4) DP_STEP(5) DP_STEP(6) DP_STEP(7)
        if (edge && lane == 31)      // release orders the remote ring stores above
            asm volatile("st.release.cluster.shared::cluster.b32 [%0], %1;"
                         :: "r"(r_cntf), "r"(p) : "memory");
        __syncthreads();
        if (rank == 1 && tid == 0)   // whole CTA1 finished phase p (incl. ring reads)
            asm volatile("st.release.cluster.shared::cluster.b32 [%0], %1;"
                         :: "r"(r_cntb), "r"(p) : "memory");
    }
#undef DP_STEP
#undef DCOMP
#undef ZLOAD

    if (rank == 1 && tid == 127) g_res[n] = resv * LN2;   // row 511: R[T,T]

    asm volatile("barrier.cluster.arrive.aligned;" ::: "memory");
    asm volatile("barrier.cluster.wait.aligned;" ::: "memory");
}

// ---------------------------------------------------------------------------
// Deterministic weighted reduction.
// ---------------------------------------------------------------------------
__global__ void reduce_kernel(const float* __restrict__ wts, float* __restrict__ out)
{
    __shared__ float s[64];
    const int tid = threadIdx.x;
    s[tid] = g_res[tid] * wts[tid];
    __syncthreads();
    #pragma unroll
    for (int off = 32; off > 0; off >>= 1) {
        if (tid < off) s[tid] += s[tid + off];
        __syncthreads();
    }
    if (tid == 0) out[0] = s[0];
}

// ---------------------------------------------------------------------------
extern "C" void kernel_launch(void* const* d_in, const int* in_sizes, int n_in,
                              void* d_out, int out_size)
{
    const float* X = nullptr; const float* wts = nullptr; const float* Z = nullptr;
    for (int i = 0; i < n_in; i++) {
        if      (in_sizes[i] == NSAMP)        wts = (const float*)d_in[i];
        else if (in_sizes[i] == TLEN * DDIM)  Z   = (const float*)d_in[i];
        else                                  X   = (const float*)d_in[i];
    }
    float* out = (float*)d_out;

    fused_dp_kernel<<<2 * NSAMP, 128>>>(X, Z);   // 64 clusters of 2 CTAs
    reduce_kernel<<<1, 64>>>(wts, out);
}

// round 13
// speedup vs baseline: 1.1650x; 1.1650x over previous
#include <cuda_runtime.h>
#include <cuda_bf16.h>
#include <math.h>

#define NSAMP 64
#define TLEN  512
#define DDIM  16
#define NDIAG 1023
#define BIGL  1.0e10f
#define LOG2E 1.4426950408889634f
#define LN2   0.6931471805599453f
#define NPHASE 135   // 8 warps, lag 8: warp 7 reaches diag 1022 at phase 134

__device__ float g_res[NSAMP];

typedef unsigned long long ull;

__device__ __forceinline__ float ex2f(float x){ float y; asm("ex2.approx.ftz.f32 %0, %1;" : "=f"(y) : "f"(x)); return y; }
__device__ __forceinline__ float lg2f(float x){ float y; asm("lg2.approx.ftz.f32 %0, %1;" : "=f"(y) : "f"(x)); return y; }
__device__ __forceinline__ ull mul2(ull a, ull b){ ull d; asm("mul.rn.f32x2 %0, %1, %2;" : "=l"(d) : "l"(a), "l"(b)); return d; }
__device__ __forceinline__ ull add2(ull a, ull b){ ull d; asm("add.rn.f32x2 %0, %1, %2;" : "=l"(d) : "l"(a), "l"(b)); return d; }
__device__ __forceinline__ ull fma2(ull a, ull b, ull c){ ull d; asm("fma.rn.f32x2 %0, %1, %2, %3;" : "=l"(d) : "l"(a), "l"(b), "l"(c)); return d; }
#define UNPK(LO, HI, P) asm("mov.b64 {%0, %1}, %2;" : "=f"(LO), "=f"(HI) : "l"(P))

// Z permutation: row z -> slot (z>>1) + 256*(z&1); lanes (2 rows apart) hit
// consecutive slots; 18-float pitch => conflict-free (validated in R12).
#define ZSLOT(z) (((z) >> 1) + 256 * ((z) & 1))

// ---------------------------------------------------------------------------
// FUSED soft-DTW: 1 CTA per sample, 256 threads = 8 warps (2/SMSP for latency
// hiding), 2 cells/thread (rows 2t, 2t+1). Staircase lag 8, rings[9][32]
// (slot-safety proven in R9). D computed on the fly one diagonal ahead from a
// parity-indexed 2-row Z register cache; dots in packed f32x2 FMA.
// ---------------------------------------------------------------------------
__global__ void __launch_bounds__(256) fused_dp_kernel(const float* __restrict__ X,
                                                       const float* __restrict__ Z)
{
    __shared__ float zsm[512 * 18];    // permuted Z rows: 16 data + z2*log2e + pad
    __shared__ float rings[9][32];     // warp w reads rings[w], writes rings[w+1]

    const int n    = blockIdx.x;
    const int tid  = threadIdx.x;
    const int w    = tid >> 5;
    const int lane = tid & 31;
    const int row0 = 2 * tid;          // first of this thread's 2 rows

    // ---- stage Z into permuted smem (+ z2*log2e at offset 16) ----
    for (int r = tid; r < 512; r += 256) {
        const float* zg = Z + r * 16;
        float vals[16]; float s2 = 0.f;
        #pragma unroll
        for (int k = 0; k < 16; k++) { float v = zg[k]; vals[k] = v; s2 = fmaf(v, v, s2); }
        float* dst = zsm + ZSLOT(r) * 18;
        #pragma unroll
        for (int k = 0; k < 16; k++) dst[k] = vals[k];
        dst[16] = s2 * LOG2E;
    }
    for (int i = tid; i < 9 * 32; i += 256) (&rings[0][0])[i] = BIGL;

    // ---- stage this thread's 2 X rows into packed registers ----
    ull xp[2][8]; float x2L[2];
    {
        const ull* Xp = (const ull*)(X + ((size_t)n * TLEN + row0) * DDIM);
        #pragma unroll
        for (int c = 0; c < 2; c++) {
            float s2 = 0.f;
            #pragma unroll
            for (int k = 0; k < 8; k++) {
                ull p = Xp[c * 8 + k]; xp[c][k] = p;
                float lo, hi; UNPK(lo, hi, p);
                s2 = fmaf(lo, lo, fmaf(hi, hi, s2));
            }
            x2L[c] = s2 * LOG2E;
        }
    }

    float rc0 = BIGL, rc1 = BIGL, rd0 = BIGL, rd1 = BIGL;
    if (tid == 0) rd0 = 0.0f;          // corner R[0][0]
    float resv = BIGL;

    float* ringr = &rings[w][0];       // warp 0 reads a never-written BIGL row
    float* ringw = &rings[w + 1][0];

    __syncthreads();                   // zsm + rings visible

    ull   zr[2][8];                    // 2-row Z cache; slot = parity bookkeeping
    float dD[2][2];                    // D ping-pong: dD[J&1][cell]

#define ZLOAD(SLOT, JUC)                                                       \
    {                                                                          \
        int jc = (JUC); jc = jc < 0 ? 0 : (jc > 511 ? 511 : jc);               \
        const ull* zp = (const ull*)(zsm + ZSLOT(jc) * 18);                    \
        zr[SLOT][0] = zp[0]; zr[SLOT][1] = zp[1];                              \
        zr[SLOT][2] = zp[2]; zr[SLOT][3] = zp[3];                              \
        zr[SLOT][4] = zp[4]; zr[SLOT][5] = zp[5];                              \
        zr[SLOT][6] = zp[6]; zr[SLOT][7] = zp[7];                              \
    }

#define DCOMP(DST, C, SLOT, JUC)                                               \
    {                                                                          \
        int jc = (JUC); jc = jc < 0 ? 0 : (jc > 511 ? 511 : jc);               \
        float z2v = zsm[ZSLOT(jc) * 18 + 16];                                  \
        ull a0 = mul2(xp[C][0], zr[SLOT][0]);                                  \
        ull a1 = mul2(xp[C][1], zr[SLOT][1]);                                  \
        a0 = fma2(xp[C][2], zr[SLOT][2], a0);                                  \
        a1 = fma2(xp[C][3], zr[SLOT][3], a1);                                  \
        a0 = fma2(xp[C][4], zr[SLOT][4], a0);                                  \
        a1 = fma2(xp[C][5], zr[SLOT][5], a1);                                  \
        a0 = fma2(xp[C][6], zr[SLOT][6], a0);                                  \
        a1 = fma2(xp[C][7], zr[SLOT][7], a1);                                  \
        a0 = add2(a0, a1);                                                     \
        float lo, hi; UNPK(lo, hi, a0);                                        \
        float dot = lo + hi;                                                   \
        (DST) = fmaxf(fmaf(dot, -2.0f * LOG2E, x2L[C] + z2v), 0.0f);           \
    }

    // ---- prologue: prime Z cache + dD[0] for this warp's first diag ----
    const int kstart = -8 * w;         // even → slot parities compile-time
    ZLOAD(1, kstart - row0 - 1)
    ZLOAD(0, kstart - row0)
    DCOMP(dD[0][0], 0, 0, kstart - row0)
    DCOMP(dD[0][1], 1, 1, kstart - row0 - 1)
    ZLOAD(1, kstart - row0 + 1)        // cache = rows kstart-row0, kstart-row0+1

#define DP_STEP(J)                                                             \
    {                                                                          \
        const int cur = kwb + (J);                                             \
        const float bval = ringr[(cur - 1) & 31];                              \
        float upsh = __shfl_up_sync(0xffffffffu, rc1, 1);                      \
        const float u0 = (lane == 0) ? bval : upsh;                            \
        const float u1 = rc0;                                                  \
        {                                                                      \
            float m  = fminf(fminf(u0, rc0), rd0);                             \
            float Mx = fmaxf(fmaxf(u0, rc0), rd0);                             \
            float mid = ((u0 + rc0) + rd0) - m - Mx;                           \
            float s  = 1.0f + ex2f(m - mid) + ex2f(m - Mx);                    \
            float v  = (dD[(J) & 1][0] + m) - lg2f(s);                         \
            if ((unsigned)(cur - row0) >= 512u) v = BIGL;                      \
            rd0 = u0; rc0 = v;                                                 \
        }                                                                      \
        {                                                                      \
            float m  = fminf(fminf(u1, rc1), rd1);                             \
            float Mx = fmaxf(fmaxf(u1, rc1), rd1);                             \
            float mid = ((u1 + rc1) + rd1) - m - Mx;                           \
            float s  = 1.0f + ex2f(m - mid) + ex2f(m - Mx);                    \
            float v  = (dD[(J) & 1][1] + m) - lg2f(s);                         \
            if ((unsigned)(cur - row0 - 1) >= 512u) v = BIGL;                  \
            rd1 = u1; rc1 = v;                                                 \
        }                                                                      \
        if (cur == NDIAG - 1) resv = rc1;                                      \
        if (lane == 31 && (unsigned)cur < 1023u) ringw[cur & 31] = rc1;        \
        /* fused: D for diag cur+1 (cell1 reads slot J&1 BEFORE ZLOAD evicts) */ \
        DCOMP(dD[((J) + 1) & 1][0], 0, ((J) + 1) & 1, cur + 1 - row0)          \
        DCOMP(dD[((J) + 1) & 1][1], 1, ((J) + 0) & 1, cur - row0)              \
        ZLOAD((J) & 1, cur + 2 - row0)                                         \
    }

    #pragma unroll 1
    for (int p = 0; p < NPHASE; ++p) {
        const int kwb = 8 * p - 8 * w;
        DP_STEP(0) DP_STEP(1) DP_STEP(2) DP_STEP(3)
        DP_STEP(4) DP_STEP(5) DP_STEP(6) DP_STEP(7)
        __syncthreads();
    }
#undef DP_STEP
#undef DCOMP
#undef ZLOAD

    if (tid == 255) g_res[n] = resv * LN2;     // row 511 at diag 1022: R[T,T]
}

// ---------------------------------------------------------------------------
// Deterministic weighted reduction.
// ---------------------------------------------------------------------------
__global__ void reduce_kernel(const float* __restrict__ wts, float* __restrict__ out)
{
    __shared__ float s[64];
    const int tid = threadIdx.x;
    s[tid] = g_res[tid] * wts[tid];
    __syncthreads();
    #pragma unroll
    for (int off = 32; off > 0; off >>= 1) {
        if (tid < off) s[tid] += s[tid + off];
        __syncthreads();
    }
    if (tid == 0) out[0] = s[0];
}

// ---------------------------------------------------------------------------
extern "C" void kernel_launch(void* const* d_in, const int* in_sizes, int n_in,
                              void* d_out, int out_size)
{
    const float* X = nullptr; const float* wts = nullptr; const float* Z = nullptr;
    for (int i = 0; i < n_in; i++) {
        if      (in_sizes[i] == NSAMP)        wts = (const float*)d_in[i];
        else if (in_sizes[i] == TLEN * DDIM)  Z   = (const float*)d_in[i];
        else                                  X   = (const float*)d_in[i];
    }
    float* out = (float*)d_out;

    fused_dp_kernel<<<NSAMP, 256>>>(X, Z);
    reduce_kernel<<<1, 64>>>(wts, out);
}

// round 14
// speedup vs baseline: 1.3816x; 1.1859x over previous
#include <cuda_runtime.h>
#include <cuda_bf16.h>
#include <math.h>

#define NSAMP 64
#define TLEN  512
#define DDIM  16
#define NDIAG 1023
#define BIGL  1.0e10f
#define LOG2E 1.4426950408889634f
#define LN2   0.6931471805599453f
#define NPHASE 131   // consumer warps 0-3, lag 8: warp 3 hits diag 1022 at p=130

__device__ float g_res[NSAMP];

typedef unsigned long long ull;

__device__ __forceinline__ float ex2f(float x){ float y; asm("ex2.approx.ftz.f32 %0, %1;" : "=f"(y) : "f"(x)); return y; }
__device__ __forceinline__ float lg2f(float x){ float y; asm("lg2.approx.ftz.f32 %0, %1;" : "=f"(y) : "f"(x)); return y; }
__device__ __forceinline__ ull mul2(ull a, ull b){ ull d; asm("mul.rn.f32x2 %0, %1, %2;" : "=l"(d) : "l"(a), "l"(b)); return d; }
__device__ __forceinline__ ull add2(ull a, ull b){ ull d; asm("add.rn.f32x2 %0, %1, %2;" : "=l"(d) : "l"(a), "l"(b)); return d; }
__device__ __forceinline__ ull fma2(ull a, ull b, ull c){ ull d; asm("fma.rn.f32x2 %0, %1, %2, %3;" : "=l"(d) : "l"(a), "l"(b), "l"(c)); return d; }
#define UNPK(LO, HI, P) asm("mov.b64 {%0, %1}, %2;" : "=f"(LO), "=f"(HI) : "l"(P))

// Z permutation (R11-proven): row z -> slot (z>>2) + 128*(z&3); producer lanes
// are 4 z-rows apart -> consecutive slots; 18-float pitch => conflict-free.
#define ZSLOT(z) (((z) >> 2) + 128 * ((z) & 3))

// Shared layout (dynamic): zsm[512*18] | dsm[4*2*8*128] | rings[5*32]
#define ZSM_F   (512 * 18)
#define DSM_F   (4 * 2 * 8 * 128)
#define RING_F  (5 * 32)
#define SMEM_B  ((ZSM_F + DSM_F + RING_F) * 4)

// ---------------------------------------------------------------------------
// Warp-specialized fused soft-DTW. 1 CTA/sample, 256 threads.
// Warps 0-3: DP consumers (softmin wavefront, staircase lag 8, rings).
// Warps 4-7: D producers — compute D one PHASE (8 diags) ahead into a parity
// ping-pong smem buffer; the per-phase __syncthreads is the entire handoff.
// ---------------------------------------------------------------------------
__global__ void __launch_bounds__(256) fused_dp_kernel(const float* __restrict__ X,
                                                       const float* __restrict__ Z)
{
    extern __shared__ float smdyn[];
    float* zsm   = smdyn;                 // producer-only
    float* dsm   = smdyn + ZSM_F;         // D slices: [(w*2+par)*8 + j][128]
    float* rings = smdyn + ZSM_F + DSM_F; // consumer-only

    const int n    = blockIdx.x;
    const int tid  = threadIdx.x;
    const int w    = tid >> 5;
    const int lane = tid & 31;
    const bool isCons = (w < 4);

    // ---- stage Z (all threads) ----
    for (int r = tid; r < 512; r += 256) {
        const float* zg = Z + r * 16;
        float vals[16]; float s2 = 0.f;
        #pragma unroll
        for (int k = 0; k < 16; k++) { float v = zg[k]; vals[k] = v; s2 = fmaf(v, v, s2); }
        float* dst = zsm + ZSLOT(r) * 18;
        #pragma unroll
        for (int k = 0; k < 16; k++) dst[k] = vals[k];
        dst[16] = s2 * LOG2E;
    }
    for (int i = tid; i < RING_F; i += 256) rings[i] = BIGL;
    __syncthreads();                      // zsm visible to producers

    // ===== consumer state =====
    const int row0c = 4 * tid;            // rows 4t..4t+3 (tid<128 effective)
    float rc0 = BIGL, rc1 = BIGL, rc2 = BIGL, rc3 = BIGL;
    float rd0 = BIGL, rd1 = BIGL, rd2 = BIGL, rd3 = BIGL;
    if (tid == 0) rd0 = 0.0f;             // corner R[0][0]
    float resv = BIGL;
    float* ringr = rings + w * 32;        // warp 0 reads never-written BIGL row
    float* ringw = rings + (w + 1) * 32;

    // ===== producer state =====
    const int tp    = tid - 128;          // 0..127 for producers
    const int wp    = (tp >> 5) & 3;      // partner consumer warp
    const int row0p = 4 * tp;
    ull xp[4][8]; float x2L[4];
    ull zr[4][8]; float z2c[4];

#define ZLOAD(SLOT, JUC)                                                       \
    {                                                                          \
        int jc = (JUC); jc = jc < 0 ? 0 : (jc > 511 ? 511 : jc);               \
        const ull* zp = (const ull*)(zsm + ZSLOT(jc) * 18);                    \
        zr[SLOT][0] = zp[0]; zr[SLOT][1] = zp[1];                              \
        zr[SLOT][2] = zp[2]; zr[SLOT][3] = zp[3];                              \
        zr[SLOT][4] = zp[4]; zr[SLOT][5] = zp[5];                              \
        zr[SLOT][6] = zp[6]; zr[SLOT][7] = zp[7];                              \
        z2c[SLOT] = zsm[ZSLOT(jc) * 18 + 16];                                  \
    }

#define DCOMP(DST, C, SLOT)                                                    \
    {                                                                          \
        ull a0 = mul2(xp[C][0], zr[SLOT][0]);                                  \
        ull a1 = mul2(xp[C][1], zr[SLOT][1]);                                  \
        a0 = fma2(xp[C][2], zr[SLOT][2], a0);                                  \
        a1 = fma2(xp[C][3], zr[SLOT][3], a1);                                  \
        a0 = fma2(xp[C][4], zr[SLOT][4], a0);                                  \
        a1 = fma2(xp[C][5], zr[SLOT][5], a1);                                  \
        a0 = fma2(xp[C][6], zr[SLOT][6], a0);                                  \
        a1 = fma2(xp[C][7], zr[SLOT][7], a1);                                  \
        a0 = add2(a0, a1);                                                     \
        float lo, hi; UNPK(lo, hi, a0);                                        \
        float dot = lo + hi;                                                   \
        (DST) = fmaxf(fmaf(dot, -2.0f * LOG2E, x2L[C] + z2c[SLOT]), 0.0f);     \
    }

// Producer: compute D[cur2][row0p+c] (c=0..3), store float4, advance Z cache.
// Slot identity: slot(z) = (z+row0p)&3; cur2 ≡ J (mod 4) ⇒ cell c uses (J-c)&3.
#define PROD_STEP(J, PB, PDST)                                                 \
    {                                                                          \
        const int cur2 = (PB) + (J);                                           \
        float dv0, dv1, dv2, dv3;                                              \
        DCOMP(dv0, 0, ((J) + 0) & 3)                                           \
        DCOMP(dv1, 1, ((J) + 3) & 3)                                           \
        DCOMP(dv2, 2, ((J) + 2) & 3)                                           \
        DCOMP(dv3, 3, ((J) + 1) & 3)                                           \
        *(float4*)((PDST) + (J) * 128) = make_float4(dv0, dv1, dv2, dv3);      \
        ZLOAD(((J) + 1) & 3, cur2 + 1 - row0p)                                 \
    }

    if (!isCons) {
        // stage this producer's 4 X rows into packed registers
        const ull* Xp = (const ull*)(X + ((size_t)n * TLEN + row0p) * DDIM);
        #pragma unroll
        for (int c = 0; c < 4; c++) {
            float s2 = 0.f;
            #pragma unroll
            for (int k = 0; k < 8; k++) {
                ull pk = Xp[c * 8 + k]; xp[c][k] = pk;
                float lo, hi; UNPK(lo, hi, pk);
                s2 = fmaf(lo, lo, fmaf(hi, hi, s2));
            }
            x2L[c] = s2 * LOG2E;
        }
        // prime Z cache for diag P0 = -8*wp: slots 1,2,3,0 hold z = P0-row0p-3..0
        const int P0 = -8 * wp;
        ZLOAD(1, P0 - row0p - 3)
        ZLOAD(2, P0 - row0p - 2)
        ZLOAD(3, P0 - row0p - 1)
        ZLOAD(0, P0 - row0p - 0)
        // prologue: fill parity-0 slices (phase 0 diags P0..P0+7)
        float* pdst = dsm + (wp * 2 + 0) * 1024 + 4 * lane;
        PROD_STEP(0, P0, pdst) PROD_STEP(1, P0, pdst)
        PROD_STEP(2, P0, pdst) PROD_STEP(3, P0, pdst)
        PROD_STEP(4, P0, pdst) PROD_STEP(5, P0, pdst)
        PROD_STEP(6, P0, pdst) PROD_STEP(7, P0, pdst)
    }
    __syncthreads();                      // phase-0 D + rings visible

// Consumer: R11 softmin core, D from one float4 LDS (lanes 16B apart: no conflicts).
#define CONS_STEP(J, KWB, DSL)                                                 \
    {                                                                          \
        const int cur = (KWB) + (J);                                           \
        const float bval = ringr[(cur - 1) & 31];                              \
        float upsh = __shfl_up_sync(0xffffffffu, rc3, 1);                      \
        const float u0 = (lane == 0) ? bval : upsh;                            \
        const float u1 = rc0, u2 = rc1, u3 = rc2;                              \
        const float4 d4 = *(const float4*)((DSL) + (J) * 128);                 \
        {                                                                      \
            float m  = fminf(fminf(u0, rc0), rd0);                             \
            float Mx = fmaxf(fmaxf(u0, rc0), rd0);                             \
            float mid = ((u0 + rc0) + rd0) - m - Mx;                           \
            float s  = 1.0f + ex2f(m - mid) + ex2f(m - Mx);                    \
            float v  = (d4.x + m) - lg2f(s);                                   \
            if ((unsigned)(cur - (row0c + 0)) >= 512u) v = BIGL;               \
            rd0 = u0; rc0 = v;                                                 \
        }                                                                      \
        {                                                                      \
            float m  = fminf(fminf(u1, rc1), rd1);                             \
            float Mx = fmaxf(fmaxf(u1, rc1), rd1);                             \
            float mid = ((u1 + rc1) + rd1) - m - Mx;                           \
            float s  = 1.0f + ex2f(m - mid) + ex2f(m - Mx);                    \
            float v  = (d4.y + m) - lg2f(s);                                   \
            if ((unsigned)(cur - (row0c + 1)) >= 512u) v = BIGL;               \
            rd1 = u1; rc1 = v;                                                 \
        }                                                                      \
        {                                                                      \
            float m  = fminf(fminf(u2, rc2), rd2);                             \
            float Mx = fmaxf(fmaxf(u2, rc2), rd2);                             \
            float mid = ((u2 + rc2) + rd2) - m - Mx;                           \
            float s  = 1.0f + ex2f(m - mid) + ex2f(m - Mx);                    \
            float v  = (d4.z + m) - lg2f(s);                                   \
            if ((unsigned)(cur - (row0c + 2)) >= 512u) v = BIGL;               \
            rd2 = u2; rc2 = v;                                                 \
        }                                                                      \
        {                                                                      \
            float m  = fminf(fminf(u3, rc3), rd3);                             \
            float Mx = fmaxf(fmaxf(u3, rc3), rd3);                             \
            float mid = ((u3 + rc3) + rd3) - m - Mx;                           \
            float s  = 1.0f + ex2f(m - mid) + ex2f(m - Mx);                    \
            float v  = (d4.w + m) - lg2f(s);                                   \
            if ((unsigned)(cur - (row0c + 3)) >= 512u) v = BIGL;               \
            rd3 = u3; rc3 = v;                                                 \
        }                                                                      \
        if (cur == NDIAG - 1) resv = rc3;                                      \
        if (lane == 31 && (unsigned)cur < 1023u) ringw[cur & 31] = rc3;        \
    }

    #pragma unroll 1
    for (int p = 0; p < NPHASE; ++p) {
        if (isCons) {
            const int kwb = 8 * p - 8 * w;
            const float* dsl = dsm + (w * 2 + (p & 1)) * 1024 + 4 * lane;
            CONS_STEP(0, kwb, dsl) CONS_STEP(1, kwb, dsl)
            CONS_STEP(2, kwb, dsl) CONS_STEP(3, kwb, dsl)
            CONS_STEP(4, kwb, dsl) CONS_STEP(5, kwb, dsl)
            CONS_STEP(6, kwb, dsl) CONS_STEP(7, kwb, dsl)
        } else {
            const int pb = 8 * (p + 1) - 8 * wp;   // one phase ahead
            float* pdst = dsm + (wp * 2 + ((p + 1) & 1)) * 1024 + 4 * lane;
            PROD_STEP(0, pb, pdst) PROD_STEP(1, pb, pdst)
            PROD_STEP(2, pb, pdst) PROD_STEP(3, pb, pdst)
            PROD_STEP(4, pb, pdst) PROD_STEP(5, pb, pdst)
            PROD_STEP(6, pb, pdst) PROD_STEP(7, pb, pdst)
        }
        __syncthreads();
    }
#undef CONS_STEP
#undef PROD_STEP
#undef DCOMP
#undef ZLOAD

    if (tid == 127) g_res[n] = resv * LN2;   // consumer warp 3: row 511, diag 1022
}

// ---------------------------------------------------------------------------
// Deterministic weighted reduction.
// ---------------------------------------------------------------------------
__global__ void reduce_kernel(const float* __restrict__ wts, float* __restrict__ out)
{
    __shared__ float s[64];
    const int tid = threadIdx.x;
    s[tid] = g_res[tid] * wts[tid];
    __syncthreads();
    #pragma unroll
    for (int off = 32; off > 0; off >>= 1) {
        if (tid < off) s[tid] += s[tid + off];
        __syncthreads();
    }
    if (tid == 0) out[0] = s[0];
}

// ---------------------------------------------------------------------------
extern "C" void kernel_launch(void* const* d_in, const int* in_sizes, int n_in,
                              void* d_out, int out_size)
{
    const float* X = nullptr; const float* wts = nullptr; const float* Z = nullptr;
    for (int i = 0; i < n_in; i++) {
        if      (in_sizes[i] == NSAMP)        wts = (const float*)d_in[i];
        else if (in_sizes[i] == TLEN * DDIM)  Z   = (const float*)d_in[i];
        else                                  X   = (const float*)d_in[i];
    }
    float* out = (float*)d_out;

    cudaFuncSetAttribute(fused_dp_kernel, cudaFuncAttributeMaxDynamicSharedMemorySize, SMEM_B);
    fused_dp_kernel<<<NSAMP, 256, SMEM_B>>>(X, Z);
    reduce_kernel<<<1, 64>>>(wts, out);
}

// round 15
// speedup vs baseline: 1.4106x; 1.0210x over previous
#include <cuda_runtime.h>
#include <cuda_bf16.h>
#include <math.h>

#define NSAMP 64
#define TLEN  512
#define DDIM  16
#define NDIAG 1023
#define BIGL  1.0e10f
#define LOG2E 1.4426950408889634f
#define LN2   0.6931471805599453f
#define NPHASE 131   // 4 warps, lag 8: warp 3 reaches diag 1022 at phase 130

__device__ float g_res[NSAMP];

typedef unsigned long long ull;

__device__ __forceinline__ float ex2f(float x){ float y; asm("ex2.approx.ftz.f32 %0, %1;" : "=f"(y) : "f"(x)); return y; }
__device__ __forceinline__ float lg2f(float x){ float y; asm("lg2.approx.ftz.f32 %0, %1;" : "=f"(y) : "f"(x)); return y; }
__device__ __forceinline__ ull mul2(ull a, ull b){ ull d; asm("mul.rn.f32x2 %0, %1, %2;" : "=l"(d) : "l"(a), "l"(b)); return d; }
__device__ __forceinline__ ull add2(ull a, ull b){ ull d; asm("add.rn.f32x2 %0, %1, %2;" : "=l"(d) : "l"(a), "l"(b)); return d; }
__device__ __forceinline__ ull fma2(ull a, ull b, ull c){ ull d; asm("fma.rn.f32x2 %0, %1, %2, %3;" : "=l"(d) : "l"(a), "l"(b), "l"(c)); return d; }
#define UNPK(LO, HI, P) asm("mov.b64 {%0, %1}, %2;" : "=f"(LO), "=f"(HI) : "l"(P))
#define PK(P, LO, HI)   asm("mov.b64 %0, {%1, %2};" : "=l"(P) : "f"(LO), "f"(HI))

// Z permutation (R11-proven): row z -> slot (z>>2) + 128*(z&3); lanes are
// 4 z-rows apart -> consecutive slots; 18-float pitch => conflict-free.
#define ZSLOT(z) (((z) >> 2) + 128 * ((z) & 3))

// ---------------------------------------------------------------------------
// FUSED soft-DTW (R11 architecture + instruction diet).
// 1 CTA/sample, 128 threads = 4 warps (1/SMSP), 4 cells/thread.
// Staircase lag 8, rings[5][32]. D computed on the fly one diagonal ahead
// from a 4-row Z register cache (values + z2 cached; zero addressing in the
// hot path). X pre-scaled by -2*log2e. NO band mask: out-of-band cells evolve
// as ~1e10 (fp32 ULP at 1e10 = 1024, so BIGL is a fixed point) and only ever
// feed other out-of-band cells.
// ---------------------------------------------------------------------------
__global__ void __launch_bounds__(128) fused_dp_kernel(const float* __restrict__ X,
                                                       const float* __restrict__ Z)
{
    __shared__ float zsm[512 * 18];    // permuted Z rows: 16 data + z2*log2e + pad
    __shared__ float rings[5][32];     // warp w reads rings[w], writes rings[w+1]

    const int n    = blockIdx.x;
    const int tid  = threadIdx.x;
    const int w    = tid >> 5;
    const int lane = tid & 31;
    const int row0 = 4 * tid;

    // ---- stage Z into permuted smem (+ z2*log2e at offset 16) ----
    for (int r = tid; r < 512; r += 128) {
        const float* zg = Z + r * 16;
        float vals[16]; float s2 = 0.f;
        #pragma unroll
        for (int k = 0; k < 16; k++) { float v = zg[k]; vals[k] = v; s2 = fmaf(v, v, s2); }
        float* dst = zsm + ZSLOT(r) * 18;
        #pragma unroll
        for (int k = 0; k < 16; k++) dst[k] = vals[k];
        dst[16] = s2 * LOG2E;
    }
    for (int i = tid; i < 5 * 32; i += 128) (&rings[0][0])[i] = BIGL;

    // ---- stage X rows 4t..4t+3, pre-scaled by -2*log2e; x2L = x2*log2e ----
    ull xp[4][8]; float x2L[4];
    {
        const ull* Xp = (const ull*)(X + ((size_t)n * TLEN + row0) * DDIM);
        #pragma unroll
        for (int c = 0; c < 4; c++) {
            float s2 = 0.f;
            #pragma unroll
            for (int k = 0; k < 8; k++) {
                ull p = Xp[c * 8 + k];
                float lo, hi; UNPK(lo, hi, p);
                s2 = fmaf(lo, lo, fmaf(hi, hi, s2));
                lo *= -2.0f * LOG2E; hi *= -2.0f * LOG2E;
                PK(xp[c][k], lo, hi);
            }
            x2L[c] = s2 * LOG2E;
        }
    }

    float rc0 = BIGL, rc1 = BIGL, rc2 = BIGL, rc3 = BIGL;
    float rd0 = BIGL, rd1 = BIGL, rd2 = BIGL, rd3 = BIGL;
    if (tid == 0) rd0 = 0.0f;          // corner R[0][0]
    float resv = BIGL;

    float* ringr = &rings[w][0];       // warp 0 reads a never-written BIGL row
    float* ringw = &rings[w + 1][0];

    __syncthreads();                   // zsm + rings visible

    ull   zr[4][8];                    // 4-row Z cache; slot(z) = (z+row0)&3
    float z2c[4];                      // cached z2*log2e per slot
    float dD[2][4];                    // D ping-pong: dD[J&1][cell]

#define ZLOAD(SLOT, JUC)                                                       \
    {                                                                          \
        int jc = (JUC); jc = jc < 0 ? 0 : (jc > 511 ? 511 : jc);               \
        const ull* zp = (const ull*)(zsm + ZSLOT(jc) * 18);                    \
        zr[SLOT][0] = zp[0]; zr[SLOT][1] = zp[1];                              \
        zr[SLOT][2] = zp[2]; zr[SLOT][3] = zp[3];                              \
        zr[SLOT][4] = zp[4]; zr[SLOT][5] = zp[5];                              \
        zr[SLOT][6] = zp[6]; zr[SLOT][7] = zp[7];                              \
        z2c[SLOT] = ((const float*)zp)[16];                                    \
    }

// D = x2L + z2 - 2*log2e*dot  (x pre-scaled; zero addressing, no clamp/fmax)
#define DCOMP(DST, C, SLOT)                                                    \
    {                                                                          \
        ull a0 = mul2(xp[C][0], zr[SLOT][0]);                                  \
        ull a1 = mul2(xp[C][1], zr[SLOT][1]);                                  \
        a0 = fma2(xp[C][2], zr[SLOT][2], a0);                                  \
        a1 = fma2(xp[C][3], zr[SLOT][3], a1);                                  \
        a0 = fma2(xp[C][4], zr[SLOT][4], a0);                                  \
        a1 = fma2(xp[C][5], zr[SLOT][5], a1);                                  \
        a0 = fma2(xp[C][6], zr[SLOT][6], a0);                                  \
        a1 = fma2(xp[C][7], zr[SLOT][7], a1);                                  \
        a0 = add2(a0, a1);                                                     \
        float lo, hi; UNPK(lo, hi, a0);                                        \
        (DST) = (lo + hi) + (x2L[C] + z2c[SLOT]);                              \
    }

    // ---- prologue: prime Z cache + dD[0] for this warp's first diag ----
    const int kstart = -8 * w;
    ZLOAD(1, kstart - 3 - row0)
    ZLOAD(2, kstart - 2 - row0)
    ZLOAD(3, kstart - 1 - row0)
    ZLOAD(0, kstart + 0 - row0)
    DCOMP(dD[0][0], 0, 0)
    DCOMP(dD[0][1], 1, 3)
    DCOMP(dD[0][2], 2, 2)
    DCOMP(dD[0][3], 3, 1)
    ZLOAD(1, kstart + 1 - row0)        // cache = rows kstart-row0-2 .. +1

#define DP_STEP(J)                                                             \
    {                                                                          \
        const int cur = kwb + (J);                                             \
        const float bval = ringr[(cur - 1) & 31];                              \
        float upsh = __shfl_up_sync(0xffffffffu, rc3, 1);                      \
        const float u0 = (lane == 0) ? bval : upsh;                            \
        const float u1 = rc0, u2 = rc1, u3 = rc2;                              \
        {                                                                      \
            float m  = fminf(fminf(u0, rc0), rd0);                             \
            float Mx = fmaxf(fmaxf(u0, rc0), rd0);                             \
            float mid = ((u0 + rc0) + rd0) - m - Mx;                           \
            float s  = 1.0f + ex2f(m - mid) + ex2f(m - Mx);                    \
            rd0 = u0; rc0 = (dD[(J) & 1][0] + m) - lg2f(s);                    \
        }                                                                      \
        {                                                                      \
            float m  = fminf(fminf(u1, rc1), rd1);                             \
            float Mx = fmaxf(fmaxf(u1, rc1), rd1);                             \
            float mid = ((u1 + rc1) + rd1) - m - Mx;                           \
            float s  = 1.0f + ex2f(m - mid) + ex2f(m - Mx);                    \
            rd1 = u1; rc1 = (dD[(J) & 1][1] + m) - lg2f(s);                    \
        }                                                                      \
        {                                                                      \
            float m  = fminf(fminf(u2, rc2), rd2);                             \
            float Mx = fmaxf(fmaxf(u2, rc2), rd2);                             \
            float mid = ((u2 + rc2) + rd2) - m - Mx;                           \
            float s  = 1.0f + ex2f(m - mid) + ex2f(m - Mx);                    \
            rd2 = u2; rc2 = (dD[(J) & 1][2] + m) - lg2f(s);                    \
        }                                                                      \
        {                                                                      \
            float m  = fminf(fminf(u3, rc3), rd3);                             \
            float Mx = fmaxf(fmaxf(u3, rc3), rd3);                             \
            float mid = ((u3 + rc3) + rd3) - m - Mx;                           \
            float s  = 1.0f + ex2f(m - mid) + ex2f(m - Mx);                    \
            rd3 = u3; rc3 = (dD[(J) & 1][3] + m) - lg2f(s);                    \
        }                                                                      \
        if (cur == NDIAG - 1) resv = rc3;          /* row 511 result snapshot */ \
        if (lane == 31) ringw[cur & 31] = rc3;                                 \
        /* fused: D for diag cur+1 (cell3 reads slot (J-2)&3 BEFORE ZLOAD) */  \
        DCOMP(dD[((J) + 1) & 1][0], 0, ((J) + 1) & 3)                          \
        DCOMP(dD[((J) + 1) & 1][1], 1, ((J) + 0) & 3)                          \
        DCOMP(dD[((J) + 1) & 1][2], 2, ((J) - 1) & 3)                          \
        DCOMP(dD[((J) + 1) & 1][3], 3, ((J) - 2) & 3)                          \
        ZLOAD(((J) + 2) & 3, cur + 2 - row0)                                   \
    }

    #pragma unroll 1
    for (int p = 0; p < NPHASE; ++p) {
        const int kwb = 8 * p - 8 * w;
        DP_STEP(0) DP_STEP(1) DP_STEP(2) DP_STEP(3)
        DP_STEP(4) DP_STEP(5) DP_STEP(6) DP_STEP(7)
        __syncthreads();
    }
#undef DP_STEP
#undef DCOMP
#undef ZLOAD

    if (tid == 127) g_res[n] = resv * LN2;     // row 511 at diag 1022: R[T,T]
}

// ---------------------------------------------------------------------------
// Deterministic weighted reduction.
// ---------------------------------------------------------------------------
__global__ void reduce_kernel(const float* __restrict__ wts, float* __restrict__ out)
{
    __shared__ float s[64];
    const int tid = threadIdx.x;
    s[tid] = g_res[tid] * wts[tid];
    __syncthreads();
    #pragma unroll
    for (int off = 32; off > 0; off >>= 1) {
        if (tid < off) s[tid] += s[tid + off];
        __syncthreads();
    }
    if (tid == 0) out[0] = s[0];
}

// ---------------------------------------------------------------------------
extern "C" void kernel_launch(void* const* d_in, const int* in_sizes, int n_in,
                              void* d_out, int out_size)
{
    const float* X = nullptr; const float* wts = nullptr; const float* Z = nullptr;
    for (int i = 0; i < n_in; i++) {
        if      (in_sizes[i] == NSAMP)        wts = (const float*)d_in[i];
        else if (in_sizes[i] == TLEN * DDIM)  Z   = (const float*)d_in[i];
        else                                  X   = (const float*)d_in[i];
    }
    float* out = (float*)d_out;

    fused_dp_kernel<<<NSAMP, 128>>>(X, Z);
    reduce_kernel<<<1, 64>>>(wts, out);
}